// round 15
// baseline (speedup 1.0000x reference)
#include <cuda_runtime.h>
#include <cuda_bf16.h>
#include <math.h>
#include <stdint.h>

#define N_NODES 50000
#define IN_CH   128
#define HID     64
#define HEADS   4
#define C1      256      // HEADS*HID
#define OUT_CH  2
#define E_BASE  800000
#define E_TOT   850000   // + self loops
#define NEG_SLOPE 0.2f
#define SCAN_BLOCKS ((N_NODES + 1023) / 1024)   // 49

// ------------------------- scratch (device globals) -------------------------
__device__ int   g_is64;
__device__ int   g_src[E_TOT];
__device__ int   g_dst[E_TOT];
__device__ int   g_deg[N_NODES];
__device__ int   g_off[N_NODES + 1];
__device__ int   g_cur[N_NODES];
__device__ int   g_csr[E_TOT];
__device__ int   g_blk[64];
__device__ float g_h1[(size_t)N_NODES * C1];     // x @ W1
__device__ float g_als1[N_NODES * HEADS];
__device__ float g_ald1[N_NODES * HEADS];
__device__ float4 g_e1[E_TOT];                   // leaky(e) per head
__device__ float g_x2[(size_t)N_NODES * C1];     // relu(agg1 + b1)
__device__ float2 g_h2[N_NODES];
__device__ float g_als2[N_NODES];
__device__ float g_ald2[N_NODES];
__device__ float g_e2[E_TOT];
// W1 transposed + split to bf16 hi/lo: [C1=256 rows (N), 128 cols (K)]
__device__ __nv_bfloat16 g_W1t_hi[C1 * IN_CH];
__device__ __nv_bfloat16 g_W1t_lo[C1 * IN_CH];

// ------------------------- helpers -------------------------
__device__ __forceinline__ float warp_sum(float v) {
#pragma unroll
    for (int o = 16; o; o >>= 1) v += __shfl_xor_sync(0xffffffffu, v, o);
    return v;
}
__device__ __forceinline__ float warp_max(float v) {
#pragma unroll
    for (int o = 16; o; o >>= 1) v = fmaxf(v, __shfl_xor_sync(0xffffffffu, v, o));
    return v;
}
__device__ __forceinline__ float lrelu(float v) { return v > 0.f ? v : NEG_SLOPE * v; }
__device__ __forceinline__ float neg_inf() { return __int_as_float(0xff800000); }

// ------------------------- init -------------------------
__global__ void k_init() {
    int i = blockIdx.x * blockDim.x + threadIdx.x;
    if (i < N_NODES) g_deg[i] = 0;
    if (i == 0) { g_is64 = 1; g_off[N_NODES] = E_TOT; }
}

__global__ void k_detect(const unsigned long long* __restrict__ ei) {
    int i = blockIdx.x * blockDim.x + threadIdx.x;
    if (i >= E_BASE) return;
    if (ei[i] >= (unsigned long long)N_NODES) g_is64 = 0;
}

__global__ void k_edges(const void* __restrict__ ei_raw) {
    int i = blockIdx.x * blockDim.x + threadIdx.x;
    if (i >= E_TOT) return;
    int s, d;
    if (i < E_BASE) {
        if (g_is64) {
            const long long* e = (const long long*)ei_raw;
            s = (int)e[i]; d = (int)e[E_BASE + i];
        } else {
            const int* e = (const int*)ei_raw;
            s = e[i]; d = e[E_BASE + i];
        }
    } else {
        s = d = i - E_BASE;
    }
    g_src[i] = s;
    g_dst[i] = d;
    atomicAdd(&g_deg[d], 1);
}

// ---------------- hierarchical exclusive scan of g_deg -> g_off -------------
__global__ void k_scan1() {
    __shared__ int ws[32];
    int i = blockIdx.x * 1024 + threadIdx.x;
    int lane = threadIdx.x & 31, w = threadIdx.x >> 5;
    int v = (i < N_NODES) ? g_deg[i] : 0;
    int s = v;
#pragma unroll
    for (int o = 1; o < 32; o <<= 1) {
        int t = __shfl_up_sync(0xffffffffu, s, o);
        if (lane >= o) s += t;
    }
    if (lane == 31) ws[w] = s;
    __syncthreads();
    if (w == 0) {
        int t = ws[lane];
#pragma unroll
        for (int o = 1; o < 32; o <<= 1) {
            int q = __shfl_up_sync(0xffffffffu, t, o);
            if (lane >= o) t += q;
        }
        ws[lane] = t;
    }
    __syncthreads();
    int excl = s - v + (w ? ws[w - 1] : 0);
    if (i < N_NODES) g_off[i] = excl;
    if (threadIdx.x == 1023) g_blk[blockIdx.x] = excl + v;
}

__global__ void k_scan2() {
    __shared__ int sh[64];
    int t = threadIdx.x;
    int v = (t < SCAN_BLOCKS) ? g_blk[t] : 0;
    sh[t] = v;
    __syncthreads();
#pragma unroll
    for (int o = 1; o < 64; o <<= 1) {
        int q = (t >= o) ? sh[t - o] : 0;
        __syncthreads();
        sh[t] += q;
        __syncthreads();
    }
    g_blk[t] = sh[t] - v;
}

__global__ void k_scan3() {
    int i = blockIdx.x * 1024 + threadIdx.x;
    if (i < N_NODES) {
        int o = g_off[i] + g_blk[blockIdx.x];
        g_off[i] = o;
        g_cur[i] = o;
    }
}

__global__ void k_scatter() {
    int i = blockIdx.x * blockDim.x + threadIdx.x;
    if (i >= E_TOT) return;
    int d = g_dst[i];
    int pos = atomicAdd(&g_cur[d], 1);
    g_csr[pos] = i;
}

// ---------------- prep W1: transpose + bf16 hi/lo split ----------------
__global__ void k_prepW(const float* __restrict__ W1) {
    int t = blockIdx.x * blockDim.x + threadIdx.x;
    if (t >= IN_CH * C1) return;
    int k = t / C1, n = t % C1;                 // coalesced read over n
    float f = W1[(size_t)k * C1 + n];
    __nv_bfloat16 hi = __float2bfloat16_rn(f);
    __nv_bfloat16 lo = __float2bfloat16_rn(f - __bfloat162float(hi));
    g_W1t_hi[n * IN_CH + k] = hi;
    g_W1t_lo[n * IN_CH + k] = lo;
}

// ---------------- GEMM1 on HMMA (mma.sync bf16, hi/lo split) ----------------
// CTA: 128 rows x 128 cols; grid = (2 col-tiles, 391 row-tiles); 8 warps,
// warp tile 32x64. K_eff = 384 (3 segments of 128: hi*hi, lo*hi, hi*lo),
// processed in 6 BK=64 chunks. Fuses als1/ald1 (per-head dot) into epilogue.
#define APITCH 72   // bf16 elements per smem row (144B: bank = 4g+tg, conflict-free)

__device__ __forceinline__ void mma16816(float* d, const uint32_t* a, const uint32_t* b) {
    asm volatile(
        "mma.sync.aligned.m16n8k16.row.col.f32.bf16.bf16.f32 "
        "{%0,%1,%2,%3}, {%4,%5,%6,%7}, {%8,%9}, {%0,%1,%2,%3};"
        : "+f"(d[0]), "+f"(d[1]), "+f"(d[2]), "+f"(d[3])
        : "r"(a[0]), "r"(a[1]), "r"(a[2]), "r"(a[3]), "r"(b[0]), "r"(b[1]));
}

__global__ void __launch_bounds__(256, 2) k_gemm1(const float* __restrict__ x,
                                                  const float* __restrict__ a_src1,
                                                  const float* __restrict__ a_dst1) {
    __shared__ __nv_bfloat16 A_s[128][APITCH];
    __shared__ __nv_bfloat16 B_s[128][APITCH];
    __shared__ float s_asrc[128], s_adst[128];

    int tid = threadIdx.x;
    int wid = tid >> 5, lane = tid & 31;
    int g = lane >> 2, tg = lane & 3;
    int m0 = (wid >> 1) * 32;
    int n0 = (wid & 1) * 64;
    int row0 = blockIdx.y * 128;
    int col0 = blockIdx.x * 128;

    if (tid < 128) {
        s_asrc[tid] = a_src1[col0 + tid];
        s_adst[tid] = a_dst1[col0 + tid];
    }

    float d[2][8][4];
#pragma unroll
    for (int mi = 0; mi < 2; mi++)
#pragma unroll
        for (int nj = 0; nj < 8; nj++)
#pragma unroll
            for (int q = 0; q < 4; q++) d[mi][nj][q] = 0.f;

    for (int c = 0; c < 6; c++) {
        int seg = c >> 1;
        int coff = (c & 1) * 64;
        __syncthreads();
        // ---- load A chunk: x[row0..row0+127][coff..coff+63] -> bf16 hi/lo
        for (int t = tid; t < 128 * 16; t += 256) {
            int r = t >> 4;
            int k4 = (t & 15) * 4;
            float4 v = make_float4(0.f, 0.f, 0.f, 0.f);
            int rg = row0 + r;
            if (rg < N_NODES) v = *(const float4*)(x + (size_t)rg * IN_CH + coff + k4);
            float f[4] = {v.x, v.y, v.z, v.w};
            unsigned short o[4];
            if (seg == 1) {
#pragma unroll
                for (int i = 0; i < 4; i++) {
                    __nv_bfloat16 hi = __float2bfloat16_rn(f[i]);
                    o[i] = __bfloat16_as_ushort(
                        __float2bfloat16_rn(f[i] - __bfloat162float(hi)));
                }
            } else {
#pragma unroll
                for (int i = 0; i < 4; i++)
                    o[i] = __bfloat16_as_ushort(__float2bfloat16_rn(f[i]));
            }
            uint2 pk;
            pk.x = o[0] | ((uint32_t)o[1] << 16);
            pk.y = o[2] | ((uint32_t)o[3] << 16);
            *(uint2*)&A_s[r][k4] = pk;
        }
        // ---- load B chunk: W1t_{hi|lo}[col0+n][coff..coff+63]
        const __nv_bfloat16* Bsrc = (seg == 2) ? g_W1t_lo : g_W1t_hi;
        for (int t = tid; t < 128 * 8; t += 256) {
            int n = t >> 3;
            int k8 = (t & 7) * 8;
            uint4 v = *(const uint4*)(Bsrc + (size_t)(col0 + n) * IN_CH + coff + k8);
            *(uint4*)&B_s[n][k8] = v;
        }
        __syncthreads();
        // ---- 4 k16 steps
#pragma unroll
        for (int kk = 0; kk < 4; kk++) {
            int kb = kk * 16 + tg * 2;
            uint32_t a[2][4];
#pragma unroll
            for (int mi = 0; mi < 2; mi++) {
                int ra = m0 + mi * 16 + g;
                a[mi][0] = *(const uint32_t*)&A_s[ra][kb];
                a[mi][1] = *(const uint32_t*)&A_s[ra + 8][kb];
                a[mi][2] = *(const uint32_t*)&A_s[ra][kb + 8];
                a[mi][3] = *(const uint32_t*)&A_s[ra + 8][kb + 8];
            }
#pragma unroll
            for (int nj = 0; nj < 8; nj++) {
                int rb = n0 + nj * 8 + g;
                uint32_t b[2];
                b[0] = *(const uint32_t*)&B_s[rb][kb];
                b[1] = *(const uint32_t*)&B_s[rb][kb + 8];
                mma16816(d[0][nj], a[0], b);
                mma16816(d[1][nj], a[1], b);
            }
        }
    }

    // ---- epilogue: store h1 + fused als1/ald1 (warp cols = one head)
    int head = (col0 + n0) >> 6;
    float ps[2][2] = {{0.f, 0.f}, {0.f, 0.f}};
    float pd[2][2] = {{0.f, 0.f}, {0.f, 0.f}};
#pragma unroll
    for (int mi = 0; mi < 2; mi++) {
        int r1 = row0 + m0 + mi * 16 + g;
        int r2 = r1 + 8;
#pragma unroll
        for (int nj = 0; nj < 8; nj++) {
            int cl = n0 + nj * 8 + tg * 2;       // local col in [0,128)
            float d0 = d[mi][nj][0], d1 = d[mi][nj][1];
            float d2 = d[mi][nj][2], d3 = d[mi][nj][3];
            ps[mi][0] += d0 * s_asrc[cl] + d1 * s_asrc[cl + 1];
            ps[mi][1] += d2 * s_asrc[cl] + d3 * s_asrc[cl + 1];
            pd[mi][0] += d0 * s_adst[cl] + d1 * s_adst[cl + 1];
            pd[mi][1] += d2 * s_adst[cl] + d3 * s_adst[cl + 1];
            if (r1 < N_NODES)
                *(float2*)(g_h1 + (size_t)r1 * C1 + col0 + cl) = make_float2(d0, d1);
            if (r2 < N_NODES)
                *(float2*)(g_h1 + (size_t)r2 * C1 + col0 + cl) = make_float2(d2, d3);
        }
    }
#pragma unroll
    for (int o = 1; o <= 2; o <<= 1) {
#pragma unroll
        for (int mi = 0; mi < 2; mi++)
#pragma unroll
            for (int q = 0; q < 2; q++) {
                ps[mi][q] += __shfl_xor_sync(0xffffffffu, ps[mi][q], o);
                pd[mi][q] += __shfl_xor_sync(0xffffffffu, pd[mi][q], o);
            }
    }
    if (tg == 0) {
#pragma unroll
        for (int mi = 0; mi < 2; mi++) {
            int r1 = row0 + m0 + mi * 16 + g;
            int r2 = r1 + 8;
            if (r1 < N_NODES) {
                g_als1[r1 * 4 + head] = ps[mi][0];
                g_ald1[r1 * 4 + head] = pd[mi][0];
            }
            if (r2 < N_NODES) {
                g_als1[r2 * 4 + head] = ps[mi][1];
                g_ald1[r2 * 4 + head] = pd[mi][1];
            }
        }
    }
}

// ------------------------- edge logits layer 1 -------------------------
__global__ void k_e1() {
    int i = blockIdx.x * blockDim.x + threadIdx.x;
    if (i >= E_TOT) return;
    int s = g_src[i], d = g_dst[i];
    float4 a = *(const float4*)(g_als1 + s * 4);
    float4 b = *(const float4*)(g_ald1 + d * 4);
    float4 e;
    e.x = lrelu(a.x + b.x);
    e.y = lrelu(a.y + b.y);
    e.z = lrelu(a.z + b.z);
    e.w = lrelu(a.w + b.w);
    g_e1[i] = e;
}

// --------- layer-1 aggregation: warp per dst node, single-pass online softmax
__global__ void k_agg1(const float* __restrict__ b1) {
    int node = (blockIdx.x * blockDim.x + threadIdx.x) >> 5;
    int lane = threadIdx.x & 31;
    if (node >= N_NODES) return;
    int beg = g_off[node], end = g_off[node + 1];
    int h = lane >> 3;
    int cbase = lane * 8;
    const float* e1f = (const float*)g_e1;

    float m = neg_inf(), dsum = 0.f;
    float acc[8];
#pragma unroll
    for (int i = 0; i < 8; i++) acc[i] = 0.f;

    int e0 = g_csr[beg];
    int s0 = g_src[e0];
    float ev0 = e1f[(size_t)e0 * 4 + h];
    const float4* hp0 = (const float4*)(g_h1 + (size_t)s0 * C1 + cbase);
    float4 u0 = hp0[0], w0 = hp0[1];

    for (int j = beg; j < end;) {
        float ev = ev0;
        float4 u = u0, w = w0;
        int jn = j + 1;
        if (jn < end) {
            int en = g_csr[jn];
            int sn = g_src[en];
            ev0 = e1f[(size_t)en * 4 + h];
            const float4* hpn = (const float4*)(g_h1 + (size_t)sn * C1 + cbase);
            u0 = hpn[0];
            w0 = hpn[1];
        }
        float p;
        if (ev > m) {
            float sc = __expf(m - ev);
            dsum = dsum * sc + 1.f;
#pragma unroll
            for (int i = 0; i < 8; i++) acc[i] *= sc;
            m = ev;
            p = 1.f;
        } else {
            p = __expf(ev - m);
            dsum += p;
        }
        acc[0] += p * u.x; acc[1] += p * u.y; acc[2] += p * u.z; acc[3] += p * u.w;
        acc[4] += p * w.x; acc[5] += p * w.y; acc[6] += p * w.z; acc[7] += p * w.w;
        j = jn;
    }
    float inv = 1.f / (dsum + 1e-16f);
    float4 bb0 = *(const float4*)(b1 + cbase);
    float4 bb1 = *(const float4*)(b1 + cbase + 4);
    float4 o0, o1;
    o0.x = fmaxf(acc[0] * inv + bb0.x, 0.f); o0.y = fmaxf(acc[1] * inv + bb0.y, 0.f);
    o0.z = fmaxf(acc[2] * inv + bb0.z, 0.f); o0.w = fmaxf(acc[3] * inv + bb0.w, 0.f);
    o1.x = fmaxf(acc[4] * inv + bb1.x, 0.f); o1.y = fmaxf(acc[5] * inv + bb1.y, 0.f);
    o1.z = fmaxf(acc[6] * inv + bb1.z, 0.f); o1.w = fmaxf(acc[7] * inv + bb1.w, 0.f);
    float* op = g_x2 + (size_t)node * C1 + cbase;
    *(float4*)op = o0;
    *(float4*)(op + 4) = o1;
}

// ------------------------- layer 2 -------------------------
__global__ void k_h2(const float* __restrict__ W2,
                     const float* __restrict__ a_src2,
                     const float* __restrict__ a_dst2) {
    __shared__ float sW[C1 * OUT_CH];
    int tid = threadIdx.x;
    sW[tid] = W2[tid];
    sW[tid + 256] = W2[tid + 256];
    __syncthreads();

    int node = (blockIdx.x * blockDim.x + tid) >> 5;
    int lane = tid & 31;
    if (node >= N_NODES) return;
    int c = lane * 8;
    const float4* xp = (const float4*)(g_x2 + (size_t)node * C1 + c);
    float4 x0 = xp[0], x1 = xp[1];
    float xv[8] = {x0.x, x0.y, x0.z, x0.w, x1.x, x1.y, x1.z, x1.w};
    float a0 = 0.f, a1 = 0.f;
#pragma unroll
    for (int i = 0; i < 8; i++) {
        a0 += xv[i] * sW[(c + i) * 2 + 0];
        a1 += xv[i] * sW[(c + i) * 2 + 1];
    }
    a0 = warp_sum(a0);
    a1 = warp_sum(a1);
    if (lane == 0) {
        g_h2[node] = make_float2(a0, a1);
        g_als2[node] = a0 * a_src2[0] + a1 * a_src2[1];
        g_ald2[node] = a0 * a_dst2[0] + a1 * a_dst2[1];
    }
}

__global__ void k_e2() {
    int i = blockIdx.x * blockDim.x + threadIdx.x;
    if (i >= E_TOT) return;
    g_e2[i] = lrelu(g_als2[g_src[i]] + g_ald2[g_dst[i]]);
}

__global__ void k_agg2(float* __restrict__ out, const float* __restrict__ b2) {
    int node = (blockIdx.x * blockDim.x + threadIdx.x) >> 5;
    int lane = threadIdx.x & 31;
    if (node >= N_NODES) return;
    int beg = g_off[node], end = g_off[node + 1];

    float m = neg_inf(), d = 0.f, a0 = 0.f, a1 = 0.f;
    for (int j = beg + lane; j < end; j += 32) {
        int e = g_csr[j];
        float ev = g_e2[e];
        float2 hv = g_h2[g_src[e]];
        float p;
        if (ev > m) {
            float sc = __expf(m - ev);
            d = d * sc + 1.f;
            a0 *= sc;
            a1 *= sc;
            m = ev;
            p = 1.f;
        } else {
            p = __expf(ev - m);
            d += p;
        }
        a0 += p * hv.x;
        a1 += p * hv.y;
    }
    float M = warp_max(m);
    float sc = __expf(m - M);
    d *= sc; a0 *= sc; a1 *= sc;
    d = warp_sum(d);
    a0 = warp_sum(a0);
    a1 = warp_sum(a1);
    if (lane == 0) {
        float inv = 1.f / (d + 1e-16f);
        out[node * 2 + 0] = a0 * inv + b2[0];
        out[node * 2 + 1] = a1 * inv + b2[1];
    }
}

// ------------------------- launch -------------------------
extern "C" void kernel_launch(void* const* d_in, const int* in_sizes, int n_in,
                              void* d_out, int out_size) {
    const float* x      = (const float*)d_in[0];
    const void*  ei     = d_in[1];
    const float* W1     = (const float*)d_in[2];
    const float* a_src1 = (const float*)d_in[3];
    const float* a_dst1 = (const float*)d_in[4];
    const float* b1     = (const float*)d_in[5];
    const float* W2     = (const float*)d_in[6];
    const float* a_src2 = (const float*)d_in[7];
    const float* a_dst2 = (const float*)d_in[8];
    const float* b2     = (const float*)d_in[9];
    float* out = (float*)d_out;

    k_init<<<(N_NODES + 255) / 256, 256>>>();
    k_detect<<<(E_BASE + 255) / 256, 256>>>((const unsigned long long*)ei);
    k_edges<<<(E_TOT + 255) / 256, 256>>>(ei);
    k_scan1<<<SCAN_BLOCKS, 1024>>>();
    k_scan2<<<1, 64>>>();
    k_scan3<<<SCAN_BLOCKS, 1024>>>();
    k_scatter<<<(E_TOT + 255) / 256, 256>>>();

    k_prepW<<<(IN_CH * C1 + 255) / 256, 256>>>(W1);
    dim3 g1(2, (N_NODES + 127) / 128);
    k_gemm1<<<g1, 256>>>(x, a_src1, a_dst1);
    k_e1<<<(E_TOT + 255) / 256, 256>>>();
    k_agg1<<<(N_NODES + 7) / 8, 256>>>(b1);

    k_h2<<<(N_NODES + 7) / 8, 256>>>(W2, a_src2, a_dst2);
    k_e2<<<(E_TOT + 255) / 256, 256>>>();
    k_agg2<<<(N_NODES + 7) / 8, 256>>>(out, b2);
}

// round 16
// speedup vs baseline: 1.0017x; 1.0017x over previous
#include <cuda_runtime.h>
#include <cuda_bf16.h>
#include <math.h>
#include <stdint.h>

#define N_NODES 50000
#define IN_CH   128
#define HID     64
#define HEADS   4
#define C1      256      // HEADS*HID
#define OUT_CH  2
#define E_BASE  800000
#define E_TOT   850000   // + self loops
#define NEG_SLOPE 0.2f
#define SCAN_BLOCKS ((N_NODES + 1023) / 1024)   // 49

// ------------------------- scratch (device globals) -------------------------
__device__ int   g_is64;
__device__ int   g_src[E_TOT];
__device__ int   g_dst[E_TOT];
__device__ int   g_deg[N_NODES];
__device__ int   g_off[N_NODES + 1];
__device__ int   g_cur[N_NODES];
__device__ int   g_csr[E_TOT];
__device__ int   g_blk[64];
__device__ float g_h1[(size_t)N_NODES * C1];     // x @ W1
__device__ float g_als1[N_NODES * HEADS];
__device__ float g_ald1[N_NODES * HEADS];
__device__ float4 g_e1[E_TOT];                   // leaky(e) per head
__device__ float g_x2[(size_t)N_NODES * C1];     // relu(agg1 + b1)
__device__ float2 g_h2[N_NODES];
__device__ float g_als2[N_NODES];
__device__ float g_ald2[N_NODES];
__device__ float g_e2[E_TOT];
// W1 transposed + split to bf16 hi/lo: [C1=256 rows (N), 128 cols (K)]
__device__ __nv_bfloat16 g_W1t_hi[C1 * IN_CH];
__device__ __nv_bfloat16 g_W1t_lo[C1 * IN_CH];

// ------------------------- helpers -------------------------
__device__ __forceinline__ float warp_sum(float v) {
#pragma unroll
    for (int o = 16; o; o >>= 1) v += __shfl_xor_sync(0xffffffffu, v, o);
    return v;
}
__device__ __forceinline__ float warp_max(float v) {
#pragma unroll
    for (int o = 16; o; o >>= 1) v = fmaxf(v, __shfl_xor_sync(0xffffffffu, v, o));
    return v;
}
__device__ __forceinline__ float lrelu(float v) { return v > 0.f ? v : NEG_SLOPE * v; }
__device__ __forceinline__ float neg_inf() { return __int_as_float(0xff800000); }

// ------------------------- init -------------------------
__global__ void k_init() {
    int i = blockIdx.x * blockDim.x + threadIdx.x;
    if (i < N_NODES) g_deg[i] = 0;
    if (i == 0) { g_is64 = 1; g_off[N_NODES] = E_TOT; }
}

__global__ void k_detect(const unsigned long long* __restrict__ ei) {
    int i = blockIdx.x * blockDim.x + threadIdx.x;
    if (i >= E_BASE) return;
    if (ei[i] >= (unsigned long long)N_NODES) g_is64 = 0;
}

__global__ void k_edges(const void* __restrict__ ei_raw) {
    int i = blockIdx.x * blockDim.x + threadIdx.x;
    if (i >= E_TOT) return;
    int s, d;
    if (i < E_BASE) {
        if (g_is64) {
            const long long* e = (const long long*)ei_raw;
            s = (int)e[i]; d = (int)e[E_BASE + i];
        } else {
            const int* e = (const int*)ei_raw;
            s = e[i]; d = e[E_BASE + i];
        }
    } else {
        s = d = i - E_BASE;
    }
    g_src[i] = s;
    g_dst[i] = d;
    atomicAdd(&g_deg[d], 1);
}

// ---------------- hierarchical exclusive scan of g_deg -> g_off -------------
__global__ void k_scan1() {
    __shared__ int ws[32];
    int i = blockIdx.x * 1024 + threadIdx.x;
    int lane = threadIdx.x & 31, w = threadIdx.x >> 5;
    int v = (i < N_NODES) ? g_deg[i] : 0;
    int s = v;
#pragma unroll
    for (int o = 1; o < 32; o <<= 1) {
        int t = __shfl_up_sync(0xffffffffu, s, o);
        if (lane >= o) s += t;
    }
    if (lane == 31) ws[w] = s;
    __syncthreads();
    if (w == 0) {
        int t = ws[lane];
#pragma unroll
        for (int o = 1; o < 32; o <<= 1) {
            int q = __shfl_up_sync(0xffffffffu, t, o);
            if (lane >= o) t += q;
        }
        ws[lane] = t;
    }
    __syncthreads();
    int excl = s - v + (w ? ws[w - 1] : 0);
    if (i < N_NODES) g_off[i] = excl;
    if (threadIdx.x == 1023) g_blk[blockIdx.x] = excl + v;
}

__global__ void k_scan2() {
    __shared__ int sh[64];
    int t = threadIdx.x;
    int v = (t < SCAN_BLOCKS) ? g_blk[t] : 0;
    sh[t] = v;
    __syncthreads();
#pragma unroll
    for (int o = 1; o < 64; o <<= 1) {
        int q = (t >= o) ? sh[t - o] : 0;
        __syncthreads();
        sh[t] += q;
        __syncthreads();
    }
    g_blk[t] = sh[t] - v;
}

__global__ void k_scan3() {
    int i = blockIdx.x * 1024 + threadIdx.x;
    if (i < N_NODES) {
        int o = g_off[i] + g_blk[blockIdx.x];
        g_off[i] = o;
        g_cur[i] = o;
    }
}

__global__ void k_scatter() {
    int i = blockIdx.x * blockDim.x + threadIdx.x;
    if (i >= E_TOT) return;
    int d = g_dst[i];
    int pos = atomicAdd(&g_cur[d], 1);
    g_csr[pos] = i;
}

// ---------------- prep W1: transpose + bf16 hi/lo split ----------------
__global__ void k_prepW(const float* __restrict__ W1) {
    int t = blockIdx.x * blockDim.x + threadIdx.x;
    if (t >= IN_CH * C1) return;
    int k = t / C1, n = t % C1;                 // coalesced read over n
    float f = W1[(size_t)k * C1 + n];
    __nv_bfloat16 hi = __float2bfloat16_rn(f);
    __nv_bfloat16 lo = __float2bfloat16_rn(f - __bfloat162float(hi));
    g_W1t_hi[n * IN_CH + k] = hi;
    g_W1t_lo[n * IN_CH + k] = lo;
}

// ---------------- GEMM1 on HMMA (mma.sync bf16, hi/lo split) ----------------
// CTA: 128 rows x 128 cols; grid = (2 col-tiles, 391 row-tiles); 8 warps,
// warp tile 32x64. K_eff = 384 (3 segments of 128: hi*hi, lo*hi, hi*lo),
// processed in 6 BK=64 chunks. Fuses als1/ald1 (per-head dot) into epilogue.
#define APITCH 72   // bf16 elements per smem row (144B: bank = 4g+tg, conflict-free)

__device__ __forceinline__ void mma16816(float* d, const uint32_t* a, const uint32_t* b) {
    asm volatile(
        "mma.sync.aligned.m16n8k16.row.col.f32.bf16.bf16.f32 "
        "{%0,%1,%2,%3}, {%4,%5,%6,%7}, {%8,%9}, {%0,%1,%2,%3};"
        : "+f"(d[0]), "+f"(d[1]), "+f"(d[2]), "+f"(d[3])
        : "r"(a[0]), "r"(a[1]), "r"(a[2]), "r"(a[3]), "r"(b[0]), "r"(b[1]));
}

__global__ void __launch_bounds__(256, 2) k_gemm1(const float* __restrict__ x,
                                                  const float* __restrict__ a_src1,
                                                  const float* __restrict__ a_dst1) {
    __shared__ __nv_bfloat16 A_s[128][APITCH];
    __shared__ __nv_bfloat16 B_s[128][APITCH];
    __shared__ float s_asrc[128], s_adst[128];

    int tid = threadIdx.x;
    int wid = tid >> 5, lane = tid & 31;
    int g = lane >> 2, tg = lane & 3;
    int m0 = (wid >> 1) * 32;
    int n0 = (wid & 1) * 64;
    int row0 = blockIdx.y * 128;
    int col0 = blockIdx.x * 128;

    if (tid < 128) {
        s_asrc[tid] = a_src1[col0 + tid];
        s_adst[tid] = a_dst1[col0 + tid];
    }

    float d[2][8][4];
#pragma unroll
    for (int mi = 0; mi < 2; mi++)
#pragma unroll
        for (int nj = 0; nj < 8; nj++)
#pragma unroll
            for (int q = 0; q < 4; q++) d[mi][nj][q] = 0.f;

    for (int c = 0; c < 6; c++) {
        int seg = c >> 1;
        int coff = (c & 1) * 64;
        __syncthreads();
        // ---- load A chunk: x[row0..row0+127][coff..coff+63] -> bf16 hi/lo
        for (int t = tid; t < 128 * 16; t += 256) {
            int r = t >> 4;
            int k4 = (t & 15) * 4;
            float4 v = make_float4(0.f, 0.f, 0.f, 0.f);
            int rg = row0 + r;
            if (rg < N_NODES) v = *(const float4*)(x + (size_t)rg * IN_CH + coff + k4);
            float f[4] = {v.x, v.y, v.z, v.w};
            unsigned short o[4];
            if (seg == 1) {
#pragma unroll
                for (int i = 0; i < 4; i++) {
                    __nv_bfloat16 hi = __float2bfloat16_rn(f[i]);
                    o[i] = __bfloat16_as_ushort(
                        __float2bfloat16_rn(f[i] - __bfloat162float(hi)));
                }
            } else {
#pragma unroll
                for (int i = 0; i < 4; i++)
                    o[i] = __bfloat16_as_ushort(__float2bfloat16_rn(f[i]));
            }
            uint2 pk;
            pk.x = o[0] | ((uint32_t)o[1] << 16);
            pk.y = o[2] | ((uint32_t)o[3] << 16);
            *(uint2*)&A_s[r][k4] = pk;
        }
        // ---- load B chunk: W1t_{hi|lo}[col0+n][coff..coff+63]
        const __nv_bfloat16* Bsrc = (seg == 2) ? g_W1t_lo : g_W1t_hi;
        for (int t = tid; t < 128 * 8; t += 256) {
            int n = t >> 3;
            int k8 = (t & 7) * 8;
            uint4 v = *(const uint4*)(Bsrc + (size_t)(col0 + n) * IN_CH + coff + k8);
            *(uint4*)&B_s[n][k8] = v;
        }
        __syncthreads();
        // ---- 4 k16 steps
#pragma unroll
        for (int kk = 0; kk < 4; kk++) {
            int kb = kk * 16 + tg * 2;
            uint32_t a[2][4];
#pragma unroll
            for (int mi = 0; mi < 2; mi++) {
                int ra = m0 + mi * 16 + g;
                a[mi][0] = *(const uint32_t*)&A_s[ra][kb];
                a[mi][1] = *(const uint32_t*)&A_s[ra + 8][kb];
                a[mi][2] = *(const uint32_t*)&A_s[ra][kb + 8];
                a[mi][3] = *(const uint32_t*)&A_s[ra + 8][kb + 8];
            }
#pragma unroll
            for (int nj = 0; nj < 8; nj++) {
                int rb = n0 + nj * 8 + g;
                uint32_t b[2];
                b[0] = *(const uint32_t*)&B_s[rb][kb];
                b[1] = *(const uint32_t*)&B_s[rb][kb + 8];
                mma16816(d[0][nj], a[0], b);
                mma16816(d[1][nj], a[1], b);
            }
        }
    }

    // ---- epilogue: store h1 + fused als1/ald1 (warp cols = one head)
    int head = (col0 + n0) >> 6;
    float ps[2][2] = {{0.f, 0.f}, {0.f, 0.f}};
    float pd[2][2] = {{0.f, 0.f}, {0.f, 0.f}};
#pragma unroll
    for (int mi = 0; mi < 2; mi++) {
        int r1 = row0 + m0 + mi * 16 + g;
        int r2 = r1 + 8;
#pragma unroll
        for (int nj = 0; nj < 8; nj++) {
            int cl = n0 + nj * 8 + tg * 2;       // local col in [0,128)
            float d0 = d[mi][nj][0], d1 = d[mi][nj][1];
            float d2 = d[mi][nj][2], d3 = d[mi][nj][3];
            ps[mi][0] += d0 * s_asrc[cl] + d1 * s_asrc[cl + 1];
            ps[mi][1] += d2 * s_asrc[cl] + d3 * s_asrc[cl + 1];
            pd[mi][0] += d0 * s_adst[cl] + d1 * s_adst[cl + 1];
            pd[mi][1] += d2 * s_adst[cl] + d3 * s_adst[cl + 1];
            if (r1 < N_NODES)
                *(float2*)(g_h1 + (size_t)r1 * C1 + col0 + cl) = make_float2(d0, d1);
            if (r2 < N_NODES)
                *(float2*)(g_h1 + (size_t)r2 * C1 + col0 + cl) = make_float2(d2, d3);
        }
    }
#pragma unroll
    for (int o = 1; o <= 2; o <<= 1) {
#pragma unroll
        for (int mi = 0; mi < 2; mi++)
#pragma unroll
            for (int q = 0; q < 2; q++) {
                ps[mi][q] += __shfl_xor_sync(0xffffffffu, ps[mi][q], o);
                pd[mi][q] += __shfl_xor_sync(0xffffffffu, pd[mi][q], o);
            }
    }
    if (tg == 0) {
#pragma unroll
        for (int mi = 0; mi < 2; mi++) {
            int r1 = row0 + m0 + mi * 16 + g;
            int r2 = r1 + 8;
            if (r1 < N_NODES) {
                g_als1[r1 * 4 + head] = ps[mi][0];
                g_ald1[r1 * 4 + head] = pd[mi][0];
            }
            if (r2 < N_NODES) {
                g_als1[r2 * 4 + head] = ps[mi][1];
                g_ald1[r2 * 4 + head] = pd[mi][1];
            }
        }
    }
}

// ------------------------- edge logits layer 1 -------------------------
__global__ void k_e1() {
    int i = blockIdx.x * blockDim.x + threadIdx.x;
    if (i >= E_TOT) return;
    int s = g_src[i], d = g_dst[i];
    float4 a = *(const float4*)(g_als1 + s * 4);
    float4 b = *(const float4*)(g_ald1 + d * 4);
    float4 e;
    e.x = lrelu(a.x + b.x);
    e.y = lrelu(a.y + b.y);
    e.z = lrelu(a.z + b.z);
    e.w = lrelu(a.w + b.w);
    g_e1[i] = e;
}

// --------- layer-1 aggregation: warp per dst node, single-pass online softmax
__global__ void k_agg1(const float* __restrict__ b1) {
    int node = (blockIdx.x * blockDim.x + threadIdx.x) >> 5;
    int lane = threadIdx.x & 31;
    if (node >= N_NODES) return;
    int beg = g_off[node], end = g_off[node + 1];
    int h = lane >> 3;
    int cbase = lane * 8;
    const float* e1f = (const float*)g_e1;

    float m = neg_inf(), dsum = 0.f;
    float acc[8];
#pragma unroll
    for (int i = 0; i < 8; i++) acc[i] = 0.f;

    int e0 = g_csr[beg];
    int s0 = g_src[e0];
    float ev0 = e1f[(size_t)e0 * 4 + h];
    const float4* hp0 = (const float4*)(g_h1 + (size_t)s0 * C1 + cbase);
    float4 u0 = hp0[0], w0 = hp0[1];

    for (int j = beg; j < end;) {
        float ev = ev0;
        float4 u = u0, w = w0;
        int jn = j + 1;
        if (jn < end) {
            int en = g_csr[jn];
            int sn = g_src[en];
            ev0 = e1f[(size_t)en * 4 + h];
            const float4* hpn = (const float4*)(g_h1 + (size_t)sn * C1 + cbase);
            u0 = hpn[0];
            w0 = hpn[1];
        }
        float p;
        if (ev > m) {
            float sc = __expf(m - ev);
            dsum = dsum * sc + 1.f;
#pragma unroll
            for (int i = 0; i < 8; i++) acc[i] *= sc;
            m = ev;
            p = 1.f;
        } else {
            p = __expf(ev - m);
            dsum += p;
        }
        acc[0] += p * u.x; acc[1] += p * u.y; acc[2] += p * u.z; acc[3] += p * u.w;
        acc[4] += p * w.x; acc[5] += p * w.y; acc[6] += p * w.z; acc[7] += p * w.w;
        j = jn;
    }
    float inv = 1.f / (dsum + 1e-16f);
    float4 bb0 = *(const float4*)(b1 + cbase);
    float4 bb1 = *(const float4*)(b1 + cbase + 4);
    float4 o0, o1;
    o0.x = fmaxf(acc[0] * inv + bb0.x, 0.f); o0.y = fmaxf(acc[1] * inv + bb0.y, 0.f);
    o0.z = fmaxf(acc[2] * inv + bb0.z, 0.f); o0.w = fmaxf(acc[3] * inv + bb0.w, 0.f);
    o1.x = fmaxf(acc[4] * inv + bb1.x, 0.f); o1.y = fmaxf(acc[5] * inv + bb1.y, 0.f);
    o1.z = fmaxf(acc[6] * inv + bb1.z, 0.f); o1.w = fmaxf(acc[7] * inv + bb1.w, 0.f);
    float* op = g_x2 + (size_t)node * C1 + cbase;
    *(float4*)op = o0;
    *(float4*)(op + 4) = o1;
}

// ------------------------- layer 2 -------------------------
__global__ void k_h2(const float* __restrict__ W2,
                     const float* __restrict__ a_src2,
                     const float* __restrict__ a_dst2) {
    __shared__ float sW[C1 * OUT_CH];
    int tid = threadIdx.x;
    sW[tid] = W2[tid];
    sW[tid + 256] = W2[tid + 256];
    __syncthreads();

    int node = (blockIdx.x * blockDim.x + tid) >> 5;
    int lane = tid & 31;
    if (node >= N_NODES) return;
    int c = lane * 8;
    const float4* xp = (const float4*)(g_x2 + (size_t)node * C1 + c);
    float4 x0 = xp[0], x1 = xp[1];
    float xv[8] = {x0.x, x0.y, x0.z, x0.w, x1.x, x1.y, x1.z, x1.w};
    float a0 = 0.f, a1 = 0.f;
#pragma unroll
    for (int i = 0; i < 8; i++) {
        a0 += xv[i] * sW[(c + i) * 2 + 0];
        a1 += xv[i] * sW[(c + i) * 2 + 1];
    }
    a0 = warp_sum(a0);
    a1 = warp_sum(a1);
    if (lane == 0) {
        g_h2[node] = make_float2(a0, a1);
        g_als2[node] = a0 * a_src2[0] + a1 * a_src2[1];
        g_ald2[node] = a0 * a_dst2[0] + a1 * a_dst2[1];
    }
}

__global__ void k_e2() {
    int i = blockIdx.x * blockDim.x + threadIdx.x;
    if (i >= E_TOT) return;
    g_e2[i] = lrelu(g_als2[g_src[i]] + g_ald2[g_dst[i]]);
}

__global__ void k_agg2(float* __restrict__ out, const float* __restrict__ b2) {
    int node = (blockIdx.x * blockDim.x + threadIdx.x) >> 5;
    int lane = threadIdx.x & 31;
    if (node >= N_NODES) return;
    int beg = g_off[node], end = g_off[node + 1];

    float m = neg_inf(), d = 0.f, a0 = 0.f, a1 = 0.f;
    for (int j = beg + lane; j < end; j += 32) {
        int e = g_csr[j];
        float ev = g_e2[e];
        float2 hv = g_h2[g_src[e]];
        float p;
        if (ev > m) {
            float sc = __expf(m - ev);
            d = d * sc + 1.f;
            a0 *= sc;
            a1 *= sc;
            m = ev;
            p = 1.f;
        } else {
            p = __expf(ev - m);
            d += p;
        }
        a0 += p * hv.x;
        a1 += p * hv.y;
    }
    float M = warp_max(m);
    float sc = __expf(m - M);
    d *= sc; a0 *= sc; a1 *= sc;
    d = warp_sum(d);
    a0 = warp_sum(a0);
    a1 = warp_sum(a1);
    if (lane == 0) {
        float inv = 1.f / (d + 1e-16f);
        out[node * 2 + 0] = a0 * inv + b2[0];
        out[node * 2 + 1] = a1 * inv + b2[1];
    }
}

// ------------------------- launch -------------------------
extern "C" void kernel_launch(void* const* d_in, const int* in_sizes, int n_in,
                              void* d_out, int out_size) {
    const float* x      = (const float*)d_in[0];
    const void*  ei     = d_in[1];
    const float* W1     = (const float*)d_in[2];
    const float* a_src1 = (const float*)d_in[3];
    const float* a_dst1 = (const float*)d_in[4];
    const float* b1     = (const float*)d_in[5];
    const float* W2     = (const float*)d_in[6];
    const float* a_src2 = (const float*)d_in[7];
    const float* a_dst2 = (const float*)d_in[8];
    const float* b2     = (const float*)d_in[9];
    float* out = (float*)d_out;

    k_init<<<(N_NODES + 255) / 256, 256>>>();
    k_detect<<<(E_BASE + 255) / 256, 256>>>((const unsigned long long*)ei);
    k_edges<<<(E_TOT + 255) / 256, 256>>>(ei);
    k_scan1<<<SCAN_BLOCKS, 1024>>>();
    k_scan2<<<1, 64>>>();
    k_scan3<<<SCAN_BLOCKS, 1024>>>();
    k_scatter<<<(E_TOT + 255) / 256, 256>>>();

    k_prepW<<<(IN_CH * C1 + 255) / 256, 256>>>(W1);
    dim3 g1(2, (N_NODES + 127) / 128);
    k_gemm1<<<g1, 256>>>(x, a_src1, a_dst1);
    k_e1<<<(E_TOT + 255) / 256, 256>>>();
    k_agg1<<<(N_NODES + 7) / 8, 256>>>(b1);

    k_h2<<<(N_NODES + 7) / 8, 256>>>(W2, a_src2, a_dst2);
    k_e2<<<(E_TOT + 255) / 256, 256>>>();
    k_agg2<<<(N_NODES + 7) / 8, 256>>>(out, b2);
}

// round 17
// speedup vs baseline: 1.1101x; 1.1082x over previous
#include <cuda_runtime.h>
#include <cuda_bf16.h>
#include <math.h>
#include <stdint.h>

#define N_NODES 50000
#define IN_CH   128
#define HID     64
#define HEADS   4
#define C1      256      // HEADS*HID
#define OUT_CH  2
#define E_BASE  800000
#define E_TOT   850000   // + self loops
#define NEG_SLOPE 0.2f
#define SCAN_BLOCKS ((N_NODES + 1023) / 1024)   // 49

// ------------------------- scratch (device globals) -------------------------
__device__ int   g_is64 = 1;   // static init; detect only ever clears it (idempotent)
__device__ int   g_src[E_TOT];
__device__ int   g_dst[E_TOT];
__device__ int   g_deg[N_NODES];
__device__ int   g_off[N_NODES + 1];
__device__ int   g_cur[N_NODES];
__device__ int   g_csr[E_TOT];
__device__ int   g_blk[64];
__device__ float g_h1[(size_t)N_NODES * C1];     // x @ W1
__device__ float g_als1[N_NODES * HEADS];
__device__ float g_ald1[N_NODES * HEADS];
__device__ float2 g_h2[N_NODES];
__device__ float g_als2[N_NODES];
__device__ float g_ald2[N_NODES];
// W1 transposed + split to bf16 hi/lo: [C1=256 rows (N), 128 cols (K)]
__device__ __nv_bfloat16 g_W1t_hi[C1 * IN_CH];
__device__ __nv_bfloat16 g_W1t_lo[C1 * IN_CH];

// ------------------------- helpers -------------------------
__device__ __forceinline__ float warp_sum(float v) {
#pragma unroll
    for (int o = 16; o; o >>= 1) v += __shfl_xor_sync(0xffffffffu, v, o);
    return v;
}
__device__ __forceinline__ float warp_max(float v) {
#pragma unroll
    for (int o = 16; o; o >>= 1) v = fmaxf(v, __shfl_xor_sync(0xffffffffu, v, o));
    return v;
}
__device__ __forceinline__ float lrelu(float v) { return v > 0.f ? v : NEG_SLOPE * v; }
__device__ __forceinline__ float neg_inf() { return __int_as_float(0xff800000); }

// ---------------- fused init + dtype detect + W1 prep ----------------
// detect: if edge_index is int64, every u64 slot < N_NODES; int32 data packs
// two indices per slot -> >= 2^32 almost everywhere. Only clears g_is64.
__global__ void k_prep(const unsigned long long* __restrict__ ei,
                       const float* __restrict__ W1) {
    int i = blockIdx.x * blockDim.x + threadIdx.x;
    if (i < N_NODES) g_deg[i] = 0;
    if (i < E_BASE && ei[i] >= (unsigned long long)N_NODES) g_is64 = 0;
    if (i < IN_CH * C1) {
        int k = i / C1, n = i % C1;             // coalesced read over n
        float f = W1[(size_t)k * C1 + n];
        __nv_bfloat16 hi = __float2bfloat16_rn(f);
        __nv_bfloat16 lo = __float2bfloat16_rn(f - __bfloat162float(hi));
        g_W1t_hi[n * IN_CH + k] = hi;
        g_W1t_lo[n * IN_CH + k] = lo;
    }
}

__global__ void k_edges(const void* __restrict__ ei_raw) {
    int i = blockIdx.x * blockDim.x + threadIdx.x;
    if (i >= E_TOT) return;
    int s, d;
    if (i < E_BASE) {
        if (g_is64) {
            const long long* e = (const long long*)ei_raw;
            s = (int)e[i]; d = (int)e[E_BASE + i];
        } else {
            const int* e = (const int*)ei_raw;
            s = e[i]; d = e[E_BASE + i];
        }
    } else {
        s = d = i - E_BASE;
    }
    g_src[i] = s;
    g_dst[i] = d;
    atomicAdd(&g_deg[d], 1);
}

// ---------------- hierarchical exclusive scan of g_deg -> g_off -------------
__global__ void k_scan1() {
    __shared__ int ws[32];
    int i = blockIdx.x * 1024 + threadIdx.x;
    int lane = threadIdx.x & 31, w = threadIdx.x >> 5;
    int v = (i < N_NODES) ? g_deg[i] : 0;
    int s = v;
#pragma unroll
    for (int o = 1; o < 32; o <<= 1) {
        int t = __shfl_up_sync(0xffffffffu, s, o);
        if (lane >= o) s += t;
    }
    if (lane == 31) ws[w] = s;
    __syncthreads();
    if (w == 0) {
        int t = ws[lane];
#pragma unroll
        for (int o = 1; o < 32; o <<= 1) {
            int q = __shfl_up_sync(0xffffffffu, t, o);
            if (lane >= o) t += q;
        }
        ws[lane] = t;
    }
    __syncthreads();
    int excl = s - v + (w ? ws[w - 1] : 0);
    if (i < N_NODES) g_off[i] = excl;
    if (threadIdx.x == 1023) g_blk[blockIdx.x] = excl + v;
}

__global__ void k_scan2() {
    __shared__ int sh[64];
    int t = threadIdx.x;
    int v = (t < SCAN_BLOCKS) ? g_blk[t] : 0;
    sh[t] = v;
    __syncthreads();
#pragma unroll
    for (int o = 1; o < 64; o <<= 1) {
        int q = (t >= o) ? sh[t - o] : 0;
        __syncthreads();
        sh[t] += q;
        __syncthreads();
    }
    g_blk[t] = sh[t] - v;
    if (t == 0) g_off[N_NODES] = E_TOT;
}

__global__ void k_scan3() {
    int i = blockIdx.x * 1024 + threadIdx.x;
    if (i < N_NODES) {
        int o = g_off[i] + g_blk[blockIdx.x];
        g_off[i] = o;
        g_cur[i] = o;
    }
}

__global__ void k_scatter() {
    int i = blockIdx.x * blockDim.x + threadIdx.x;
    if (i >= E_TOT) return;
    int d = g_dst[i];
    int pos = atomicAdd(&g_cur[d], 1);
    g_csr[pos] = i;
}

// ---------------- GEMM1 on HMMA (mma.sync bf16, hi/lo split) ----------------
// CTA: 128 rows x 128 cols; 8 warps, warp tile 32x64. K_eff = 384 (hi*hi,
// lo*hi, hi*lo), 6 BK=64 chunks. Fuses als1/ald1 into the epilogue.
#define APITCH 72   // bf16 per smem row (144B) -> conflict-free k-fragments

__device__ __forceinline__ void mma16816(float* d, const uint32_t* a, const uint32_t* b) {
    asm volatile(
        "mma.sync.aligned.m16n8k16.row.col.f32.bf16.bf16.f32 "
        "{%0,%1,%2,%3}, {%4,%5,%6,%7}, {%8,%9}, {%0,%1,%2,%3};"
        : "+f"(d[0]), "+f"(d[1]), "+f"(d[2]), "+f"(d[3])
        : "r"(a[0]), "r"(a[1]), "r"(a[2]), "r"(a[3]), "r"(b[0]), "r"(b[1]));
}

__global__ void __launch_bounds__(256, 2) k_gemm1(const float* __restrict__ x,
                                                  const float* __restrict__ a_src1,
                                                  const float* __restrict__ a_dst1) {
    __shared__ __nv_bfloat16 A_s[128][APITCH];
    __shared__ __nv_bfloat16 B_s[128][APITCH];
    __shared__ float s_asrc[128], s_adst[128];

    int tid = threadIdx.x;
    int wid = tid >> 5, lane = tid & 31;
    int g = lane >> 2, tg = lane & 3;
    int m0 = (wid >> 1) * 32;
    int n0 = (wid & 1) * 64;
    int row0 = blockIdx.y * 128;
    int col0 = blockIdx.x * 128;

    if (tid < 128) {
        s_asrc[tid] = a_src1[col0 + tid];
        s_adst[tid] = a_dst1[col0 + tid];
    }

    float d[2][8][4];
#pragma unroll
    for (int mi = 0; mi < 2; mi++)
#pragma unroll
        for (int nj = 0; nj < 8; nj++)
#pragma unroll
            for (int q = 0; q < 4; q++) d[mi][nj][q] = 0.f;

    for (int c = 0; c < 6; c++) {
        int seg = c >> 1;
        int coff = (c & 1) * 64;
        __syncthreads();
        for (int t = tid; t < 128 * 16; t += 256) {
            int r = t >> 4;
            int k4 = (t & 15) * 4;
            float4 v = make_float4(0.f, 0.f, 0.f, 0.f);
            int rg = row0 + r;
            if (rg < N_NODES) v = *(const float4*)(x + (size_t)rg * IN_CH + coff + k4);
            float f[4] = {v.x, v.y, v.z, v.w};
            unsigned short o[4];
            if (seg == 1) {
#pragma unroll
                for (int i = 0; i < 4; i++) {
                    __nv_bfloat16 hi = __float2bfloat16_rn(f[i]);
                    o[i] = __bfloat16_as_ushort(
                        __float2bfloat16_rn(f[i] - __bfloat162float(hi)));
                }
            } else {
#pragma unroll
                for (int i = 0; i < 4; i++)
                    o[i] = __bfloat16_as_ushort(__float2bfloat16_rn(f[i]));
            }
            uint2 pk;
            pk.x = o[0] | ((uint32_t)o[1] << 16);
            pk.y = o[2] | ((uint32_t)o[3] << 16);
            *(uint2*)&A_s[r][k4] = pk;
        }
        const __nv_bfloat16* Bsrc = (seg == 2) ? g_W1t_lo : g_W1t_hi;
        for (int t = tid; t < 128 * 8; t += 256) {
            int n = t >> 3;
            int k8 = (t & 7) * 8;
            uint4 v = *(const uint4*)(Bsrc + (size_t)(col0 + n) * IN_CH + coff + k8);
            *(uint4*)&B_s[n][k8] = v;
        }
        __syncthreads();
#pragma unroll
        for (int kk = 0; kk < 4; kk++) {
            int kb = kk * 16 + tg * 2;
            uint32_t a[2][4];
#pragma unroll
            for (int mi = 0; mi < 2; mi++) {
                int ra = m0 + mi * 16 + g;
                a[mi][0] = *(const uint32_t*)&A_s[ra][kb];
                a[mi][1] = *(const uint32_t*)&A_s[ra + 8][kb];
                a[mi][2] = *(const uint32_t*)&A_s[ra][kb + 8];
                a[mi][3] = *(const uint32_t*)&A_s[ra + 8][kb + 8];
            }
#pragma unroll
            for (int nj = 0; nj < 8; nj++) {
                int rb = n0 + nj * 8 + g;
                uint32_t b[2];
                b[0] = *(const uint32_t*)&B_s[rb][kb];
                b[1] = *(const uint32_t*)&B_s[rb][kb + 8];
                mma16816(d[0][nj], a[0], b);
                mma16816(d[1][nj], a[1], b);
            }
        }
    }

    int head = (col0 + n0) >> 6;
    float ps[2][2] = {{0.f, 0.f}, {0.f, 0.f}};
    float pd[2][2] = {{0.f, 0.f}, {0.f, 0.f}};
#pragma unroll
    for (int mi = 0; mi < 2; mi++) {
        int r1 = row0 + m0 + mi * 16 + g;
        int r2 = r1 + 8;
#pragma unroll
        for (int nj = 0; nj < 8; nj++) {
            int cl = n0 + nj * 8 + tg * 2;
            float d0 = d[mi][nj][0], d1 = d[mi][nj][1];
            float d2 = d[mi][nj][2], d3 = d[mi][nj][3];
            ps[mi][0] += d0 * s_asrc[cl] + d1 * s_asrc[cl + 1];
            ps[mi][1] += d2 * s_asrc[cl] + d3 * s_asrc[cl + 1];
            pd[mi][0] += d0 * s_adst[cl] + d1 * s_adst[cl + 1];
            pd[mi][1] += d2 * s_adst[cl] + d3 * s_adst[cl + 1];
            if (r1 < N_NODES)
                *(float2*)(g_h1 + (size_t)r1 * C1 + col0 + cl) = make_float2(d0, d1);
            if (r2 < N_NODES)
                *(float2*)(g_h1 + (size_t)r2 * C1 + col0 + cl) = make_float2(d2, d3);
        }
    }
#pragma unroll
    for (int o = 1; o <= 2; o <<= 1) {
#pragma unroll
        for (int mi = 0; mi < 2; mi++)
#pragma unroll
            for (int q = 0; q < 2; q++) {
                ps[mi][q] += __shfl_xor_sync(0xffffffffu, ps[mi][q], o);
                pd[mi][q] += __shfl_xor_sync(0xffffffffu, pd[mi][q], o);
            }
    }
    if (tg == 0) {
#pragma unroll
        for (int mi = 0; mi < 2; mi++) {
            int r1 = row0 + m0 + mi * 16 + g;
            int r2 = r1 + 8;
            if (r1 < N_NODES) {
                g_als1[r1 * 4 + head] = ps[mi][0];
                g_ald1[r1 * 4 + head] = pd[mi][0];
            }
            if (r2 < N_NODES) {
                g_als1[r2 * 4 + head] = ps[mi][1];
                g_ald1[r2 * 4 + head] = pd[mi][1];
            }
        }
    }
}

// ---- layer-1 aggregation, FULLY FUSED: on-the-fly edge logits, online
// softmax, bias+relu, layer-2 GEMV (h2), and layer-2 logits (als2/ald2).
// Never materializes e1 or x2. Warp per dst node.
__global__ void k_agg1(const float* __restrict__ b1, const float* __restrict__ W2,
                       const float* __restrict__ a_src2,
                       const float* __restrict__ a_dst2) {
    int node = (blockIdx.x * blockDim.x + threadIdx.x) >> 5;
    int lane = threadIdx.x & 31;
    if (node >= N_NODES) return;
    int beg = g_off[node], end = g_off[node + 1];
    int h = lane >> 3;
    int cbase = lane * 8;

    float eld = g_ald1[node * 4 + h];   // loop-invariant dst logit

    float m = neg_inf(), dsum = 0.f;
    float acc[8];
#pragma unroll
    for (int i = 0; i < 8; i++) acc[i] = 0.f;

    int e0 = g_csr[beg];
    int s0 = g_src[e0];
    float ev0 = lrelu(g_als1[s0 * 4 + h] + eld);
    const float4* hp0 = (const float4*)(g_h1 + (size_t)s0 * C1 + cbase);
    float4 u0 = hp0[0], w0 = hp0[1];

    for (int j = beg; j < end;) {
        float ev = ev0;
        float4 u = u0, w = w0;
        int jn = j + 1;
        if (jn < end) {
            int en = g_csr[jn];
            int sn = g_src[en];
            ev0 = lrelu(g_als1[sn * 4 + h] + eld);
            const float4* hpn = (const float4*)(g_h1 + (size_t)sn * C1 + cbase);
            u0 = hpn[0];
            w0 = hpn[1];
        }
        float p;
        if (ev > m) {
            float sc = __expf(m - ev);   // first iter: exp(-inf) = 0
            dsum = dsum * sc + 1.f;
#pragma unroll
            for (int i = 0; i < 8; i++) acc[i] *= sc;
            m = ev;
            p = 1.f;
        } else {
            p = __expf(ev - m);
            dsum += p;
        }
        acc[0] += p * u.x; acc[1] += p * u.y; acc[2] += p * u.z; acc[3] += p * u.w;
        acc[4] += p * w.x; acc[5] += p * w.y; acc[6] += p * w.z; acc[7] += p * w.w;
        j = jn;
    }
    float inv = 1.f / (dsum + 1e-16f);
    float4 bb0 = *(const float4*)(b1 + cbase);
    float4 bb1 = *(const float4*)(b1 + cbase + 4);
    float o[8];
    o[0] = fmaxf(acc[0] * inv + bb0.x, 0.f); o[1] = fmaxf(acc[1] * inv + bb0.y, 0.f);
    o[2] = fmaxf(acc[2] * inv + bb0.z, 0.f); o[3] = fmaxf(acc[3] * inv + bb0.w, 0.f);
    o[4] = fmaxf(acc[4] * inv + bb1.x, 0.f); o[5] = fmaxf(acc[5] * inv + bb1.y, 0.f);
    o[6] = fmaxf(acc[6] * inv + bb1.z, 0.f); o[7] = fmaxf(acc[7] * inv + bb1.w, 0.f);

    // fused layer-2 GEMV: W2 rows [cbase..cbase+7], 2 out channels
    const float4* wp = (const float4*)(W2 + cbase * 2);
    float a0 = 0.f, a1 = 0.f;
#pragma unroll
    for (int i = 0; i < 4; i++) {
        float4 q = wp[i];                     // {W2[c][0],W2[c][1],W2[c+1][0],W2[c+1][1]}
        a0 += o[i * 2] * q.x + o[i * 2 + 1] * q.z;
        a1 += o[i * 2] * q.y + o[i * 2 + 1] * q.w;
    }
    a0 = warp_sum(a0);
    a1 = warp_sum(a1);
    if (lane == 0) {
        g_h2[node] = make_float2(a0, a1);
        g_als2[node] = a0 * __ldg(a_src2) + a1 * __ldg(a_src2 + 1);
        g_ald2[node] = a0 * __ldg(a_dst2) + a1 * __ldg(a_dst2 + 1);
    }
}

// ---- layer-2 aggregation: on-the-fly logits + online softmax ----
__global__ void k_agg2(float* __restrict__ out, const float* __restrict__ b2) {
    int node = (blockIdx.x * blockDim.x + threadIdx.x) >> 5;
    int lane = threadIdx.x & 31;
    if (node >= N_NODES) return;
    int beg = g_off[node], end = g_off[node + 1];
    float eld = g_ald2[node];

    float m = neg_inf(), d = 0.f, a0 = 0.f, a1 = 0.f;
    for (int j = beg + lane; j < end; j += 32) {
        int e = g_csr[j];
        int s = g_src[e];
        float ev = lrelu(g_als2[s] + eld);
        float2 hv = g_h2[s];
        float p;
        if (ev > m) {
            float sc = __expf(m - ev);
            d = d * sc + 1.f;
            a0 *= sc;
            a1 *= sc;
            m = ev;
            p = 1.f;
        } else {
            p = __expf(ev - m);
            d += p;
        }
        a0 += p * hv.x;
        a1 += p * hv.y;
    }
    float M = warp_max(m);
    float sc = __expf(m - M);
    d *= sc; a0 *= sc; a1 *= sc;
    d = warp_sum(d);
    a0 = warp_sum(a0);
    a1 = warp_sum(a1);
    if (lane == 0) {
        float inv = 1.f / (d + 1e-16f);
        out[node * 2 + 0] = a0 * inv + b2[0];
        out[node * 2 + 1] = a1 * inv + b2[1];
    }
}

// ------------------------- launch -------------------------
extern "C" void kernel_launch(void* const* d_in, const int* in_sizes, int n_in,
                              void* d_out, int out_size) {
    const float* x      = (const float*)d_in[0];
    const void*  ei     = d_in[1];
    const float* W1     = (const float*)d_in[2];
    const float* a_src1 = (const float*)d_in[3];
    const float* a_dst1 = (const float*)d_in[4];
    const float* b1     = (const float*)d_in[5];
    const float* W2     = (const float*)d_in[6];
    const float* a_src2 = (const float*)d_in[7];
    const float* a_dst2 = (const float*)d_in[8];
    const float* b2     = (const float*)d_in[9];
    float* out = (float*)d_out;

    k_prep<<<(E_BASE + 255) / 256, 256>>>((const unsigned long long*)ei, W1);
    k_edges<<<(E_TOT + 255) / 256, 256>>>(ei);
    k_scan1<<<SCAN_BLOCKS, 1024>>>();
    k_scan2<<<1, 64>>>();
    k_scan3<<<SCAN_BLOCKS, 1024>>>();
    k_scatter<<<(E_TOT + 255) / 256, 256>>>();

    dim3 g1(2, (N_NODES + 127) / 128);
    k_gemm1<<<g1, 256>>>(x, a_src1, a_dst1);
    k_agg1<<<(N_NODES + 7) / 8, 256>>>(b1, W2, a_src2, a_dst2);
    k_agg2<<<(N_NODES + 7) / 8, 256>>>(out, b2);
}